// round 4
// baseline (speedup 1.0000x reference)
#include <cuda_runtime.h>
#include <stdint.h>

#define NNODES   100000
#define NGRAPHS  128
#define HDIM     256

// Scratch (no allocation allowed)
__device__ float d_agg[NNODES];
__device__ int   d_starts[NGRAPHS + 1];

// ---------------------------------------------------------------------------
// Fused kernel: blocks [0, edgeBlocks) do the edge scatter-add,
// blocks [edgeBlocks, edgeBlocks+bndBlocks) do boundary detection on the
// sorted batch array.  The boundary work (~1.5us standalone) rides for free
// inside the ~30us LSU-bound edge scatter.
//
// Edge part:  agg[dst] += x[src], 8 edges/thread, front-batched int4 index
//             loads (4x LDG.128), then 8 gathers, then 8 REDs.
// Boundary:   d_starts[g] = first i with batch[i] >= g; d_starts[G] = N.
//             int4 loads, 4 nodes/thread.
// ---------------------------------------------------------------------------
__global__ void edge_boundary_kernel(const int* __restrict__ ei,
                                     const float* __restrict__ x,
                                     const int* __restrict__ batch,
                                     int E, int N, int edgeBlocks) {
    if ((int)blockIdx.x < edgeBlocks) {
        int t = blockIdx.x * blockDim.x + threadIdx.x;
        int i = t << 3;
        if (i + 7 < E) {
            const int4* sp = reinterpret_cast<const int4*>(ei + i);
            const int4* dp = reinterpret_cast<const int4*>(ei + E + i);
            int4 s0 = __ldg(sp);
            int4 s1 = __ldg(sp + 1);
            int4 d0 = __ldg(dp);
            int4 d1 = __ldg(dp + 1);
            float v0 = __ldg(x + s0.x);
            float v1 = __ldg(x + s0.y);
            float v2 = __ldg(x + s0.z);
            float v3 = __ldg(x + s0.w);
            float v4 = __ldg(x + s1.x);
            float v5 = __ldg(x + s1.y);
            float v6 = __ldg(x + s1.z);
            float v7 = __ldg(x + s1.w);
            atomicAdd(&d_agg[d0.x], v0);
            atomicAdd(&d_agg[d0.y], v1);
            atomicAdd(&d_agg[d0.z], v2);
            atomicAdd(&d_agg[d0.w], v3);
            atomicAdd(&d_agg[d1.x], v4);
            atomicAdd(&d_agg[d1.y], v5);
            atomicAdd(&d_agg[d1.z], v6);
            atomicAdd(&d_agg[d1.w], v7);
        } else if (i < E) {
            for (int e = i; e < E; e++)
                atomicAdd(&d_agg[ei[E + e]], __ldg(x + ei[e]));
        }
    } else {
        // boundary detection, 4 nodes per thread via int4
        int t    = (blockIdx.x - edgeBlocks) * blockDim.x + threadIdx.x;
        int base = t << 2;
        if (base >= N) return;
        int b0, b1, b2, b3;
        if (base + 3 < N) {
            int4 v = __ldg(reinterpret_cast<const int4*>(batch + base));
            b0 = v.x; b1 = v.y; b2 = v.z; b3 = v.w;
        } else {
            b0 = batch[base];
            b1 = (base + 1 < N) ? batch[base + 1] : b0;
            b2 = (base + 2 < N) ? batch[base + 2] : b1;
            b3 = (base + 3 < N) ? batch[base + 3] : b2;
        }
        int prev = (base == 0) ? -1 : __ldg(batch + base - 1);
        #pragma unroll
        for (int e = 0; e < 4; e++) {
            int idx = base + e;
            int b = (e == 0) ? b0 : (e == 1) ? b1 : (e == 2) ? b2 : b3;
            if (idx < N) {
                for (int g = prev + 1; g <= b; g++) d_starts[g] = idx;
                prev = b;
                if (idx == N - 1)
                    for (int g = b + 1; g <= NGRAPHS; g++) d_starts[g] = N;
            }
        }
    }
}

// ---------------------------------------------------------------------------
// Fused  relu(agg*W_l + b_l) -> mean pool -> relu(pooled.W_out + b_out).
// One block per graph, 512 threads = 2 halves x 256 features.
// ---------------------------------------------------------------------------
__global__ __launch_bounds__(512)
void pool_kernel(const float* __restrict__ W_l,
                 const float* __restrict__ b_l,
                 const float* __restrict__ W_out,
                 const float* __restrict__ b_out,
                 float* __restrict__ out) {
    const int g = blockIdx.x;
    const int t = threadIdx.x;
    const int k = t & 255;     // feature
    const int h = t >> 8;      // half id

    const int start = d_starts[g];
    const int end   = d_starts[g + 1];
    const int len   = end - start;
    const int half0 = (len + 1) >> 1;
    const int s0    = start + h * half0;
    const int myLen = h ? (len - half0) : half0;
    const int nt    = (half0 + 255) >> 8;   // uniform tile count across block

    const float w = W_l[k];
    const float b = b_l[k];
    float acc = 0.0f;

    __shared__ float sa[2][HDIM];
    for (int it = 0; it < nt; it++) {
        const int base = it << 8;
        const int n = min(HDIM, myLen - base);    // may be <= 0 for half 1
        __syncthreads();
        if (k < n) sa[h][k] = d_agg[s0 + base + k];
        __syncthreads();
        const int n4 = n >> 2;
        const float4* sv = reinterpret_cast<const float4*>(sa[h]);
        for (int j = 0; j < n4; j++) {
            float4 v = sv[j];                      // warp-broadcast LDS.128
            acc += fmaxf(fmaf(v.x, w, b), 0.0f);
            acc += fmaxf(fmaf(v.y, w, b), 0.0f);
            acc += fmaxf(fmaf(v.z, w, b), 0.0f);
            acc += fmaxf(fmaf(v.w, w, b), 0.0f);
        }
        for (int j = n4 << 2; j < n; j++)
            acc += fmaxf(fmaf(sa[h][j], w, b), 0.0f);
    }

    const float cnt = fmaxf((float)len, 1.0f);
    float val = acc * W_out[k] / cnt;

    #pragma unroll
    for (int off = 16; off; off >>= 1)
        val += __shfl_xor_sync(0xffffffffu, val, off);
    __shared__ float warpsum[16];
    const int wid = t >> 5, lid = t & 31;
    if (lid == 0) warpsum[wid] = val;
    __syncthreads();
    if (wid == 0) {
        float v = (lid < 16) ? warpsum[lid] : 0.0f;
        #pragma unroll
        for (int off = 8; off; off >>= 1)
            v += __shfl_xor_sync(0xffffffffu, v, off);
        if (lid == 0) out[g] = fmaxf(v + b_out[0], 0.0f);
    }
}

// ---------------------------------------------------------------------------
// inputs (metadata order):
//   0: x float32[N]  1: ei int32[2E]  2: batch int32[N]
//   3: W_l f32[256]  4: b_l f32[256]  5: W_out f32[256]  6: b_out f32[1]
// out: float32 [128]
// ---------------------------------------------------------------------------
extern "C" void kernel_launch(void* const* d_in, const int* in_sizes, int n_in,
                              void* d_out, int out_size) {
    const float* x     = (const float*)d_in[0];
    const int*   ei    = (const int*)d_in[1];
    const int*   batch = (const int*)d_in[2];
    const float* W_l   = (const float*)d_in[3];
    const float* b_l   = (const float*)d_in[4];
    const float* W_out = (const float*)d_in[5];
    const float* b_out = (const float*)d_in[6];
    float*       out   = (float*)d_out;

    const int N = in_sizes[0];
    const int E = in_sizes[1] / 2;

    // zero agg via memset node
    void* aggp = nullptr;
    cudaGetSymbolAddress(&aggp, d_agg);
    cudaMemsetAsync(aggp, 0, (size_t)N * sizeof(float), 0);

    {
        const int threads    = 256;
        const int edgeWork   = (E + 7) / 8;
        const int edgeBlocks = (edgeWork + threads - 1) / threads;
        const int bndThreads = (N + 3) / 4;
        const int bndBlocks  = (bndThreads + threads - 1) / threads;
        edge_boundary_kernel<<<edgeBlocks + bndBlocks, threads>>>(
            ei, x, batch, E, N, edgeBlocks);
    }
    {
        pool_kernel<<<NGRAPHS, 512>>>(W_l, b_l, W_out, b_out, out);
    }
}

// round 5
// speedup vs baseline: 1.1165x; 1.1165x over previous
#include <cuda_runtime.h>
#include <stdint.h>

#define NNODES   100000
#define NGRAPHS  128
#define HDIM     256

// Scratch (no allocation allowed)
__device__ float d_agg[NNODES];
__device__ int   d_starts[NGRAPHS + 1];
__device__ float d_P;        // sum_{w_k>0} W_out[k]*W_l[k]
__device__ float d_Nn;       // sum_{w_k<0} W_out[k]*W_l[k]
__device__ int   d_blzero;   // 1 if all b_l == 0  -> 2-slope fast path valid

// ---------------------------------------------------------------------------
// Fused kernel:
//   blocks [0, edgeBlocks)                : edge scatter-add agg[dst]+=x[src]
//   blocks [edgeBlocks, +bndBlocks)       : boundary detect on sorted batch
//   last block                            : setup (b_l==0 flag, P, Nn)
// ---------------------------------------------------------------------------
__global__ void edge_fused_kernel(const int* __restrict__ ei,
                                  const float* __restrict__ x,
                                  const int* __restrict__ batch,
                                  const float* __restrict__ W_l,
                                  const float* __restrict__ b_l,
                                  const float* __restrict__ W_out,
                                  int E, int N, int edgeBlocks, int bndBlocks) {
    const int bid = (int)blockIdx.x;
    if (bid < edgeBlocks) {
        int t = bid * blockDim.x + threadIdx.x;
        int i = t << 3;
        if (i + 7 < E) {
            const int4* sp = reinterpret_cast<const int4*>(ei + i);
            const int4* dp = reinterpret_cast<const int4*>(ei + E + i);
            int4 s0 = __ldg(sp);
            int4 s1 = __ldg(sp + 1);
            int4 d0 = __ldg(dp);
            int4 d1 = __ldg(dp + 1);
            float v0 = __ldg(x + s0.x);
            float v1 = __ldg(x + s0.y);
            float v2 = __ldg(x + s0.z);
            float v3 = __ldg(x + s0.w);
            float v4 = __ldg(x + s1.x);
            float v5 = __ldg(x + s1.y);
            float v6 = __ldg(x + s1.z);
            float v7 = __ldg(x + s1.w);
            atomicAdd(&d_agg[d0.x], v0);
            atomicAdd(&d_agg[d0.y], v1);
            atomicAdd(&d_agg[d0.z], v2);
            atomicAdd(&d_agg[d0.w], v3);
            atomicAdd(&d_agg[d1.x], v4);
            atomicAdd(&d_agg[d1.y], v5);
            atomicAdd(&d_agg[d1.z], v6);
            atomicAdd(&d_agg[d1.w], v7);
        } else if (i < E) {
            for (int e = i; e < E; e++)
                atomicAdd(&d_agg[ei[E + e]], __ldg(x + ei[e]));
        }
    } else if (bid < edgeBlocks + bndBlocks) {
        // boundary detection, 4 nodes per thread via int4
        int t    = (bid - edgeBlocks) * blockDim.x + threadIdx.x;
        int base = t << 2;
        if (base >= N) return;
        int b0, b1, b2, b3;
        if (base + 3 < N) {
            int4 v = __ldg(reinterpret_cast<const int4*>(batch + base));
            b0 = v.x; b1 = v.y; b2 = v.z; b3 = v.w;
        } else {
            b0 = batch[base];
            b1 = (base + 1 < N) ? batch[base + 1] : b0;
            b2 = (base + 2 < N) ? batch[base + 2] : b1;
            b3 = (base + 3 < N) ? batch[base + 3] : b2;
        }
        int prev = (base == 0) ? -1 : __ldg(batch + base - 1);
        #pragma unroll
        for (int e = 0; e < 4; e++) {
            int idx = base + e;
            int b = (e == 0) ? b0 : (e == 1) ? b1 : (e == 2) ? b2 : b3;
            if (idx < N) {
                for (int g = prev + 1; g <= b; g++) d_starts[g] = idx;
                prev = b;
                if (idx == N - 1)
                    for (int g = b + 1; g <= NGRAPHS; g++) d_starts[g] = N;
            }
        }
    } else {
        // setup block: check b_l == 0 and precompute 2-slope constants
        const int k = threadIdx.x;            // 0..255
        const float b  = b_l[k];
        const float w  = W_l[k];
        const float wo = W_out[k];
        const int allz = __syncthreads_and(b == 0.0f);
        float p = (w > 0.0f) ? wo * w : 0.0f;
        float n = (w < 0.0f) ? wo * w : 0.0f;
        #pragma unroll
        for (int off = 16; off; off >>= 1) {
            p += __shfl_xor_sync(0xffffffffu, p, off);
            n += __shfl_xor_sync(0xffffffffu, n, off);
        }
        __shared__ float sp[8], sn[8];
        const int wid = k >> 5, lid = k & 31;
        if (lid == 0) { sp[wid] = p; sn[wid] = n; }
        __syncthreads();
        if (k == 0) {
            float P = 0.0f, Nn = 0.0f;
            #pragma unroll
            for (int wI = 0; wI < 8; wI++) { P += sp[wI]; Nn += sn[wI]; }
            d_P = P; d_Nn = Nn; d_blzero = allz;
        }
    }
}

// ---------------------------------------------------------------------------
// Pool: one block (256 threads) per graph.
// Fast path (b_l == 0): out[g] = relu((P*S+ + Nn*S-)/cnt + b_out),
//   S+ = sum of positive agg in range, S- = sum of negative.
// Slow path (general b_l): exact feature-parallel compute.
// ---------------------------------------------------------------------------
__global__ __launch_bounds__(HDIM)
void pool_kernel(const float* __restrict__ W_l,
                 const float* __restrict__ b_l,
                 const float* __restrict__ W_out,
                 const float* __restrict__ b_out,
                 float* __restrict__ out) {
    const int g = blockIdx.x;
    const int t = threadIdx.x;
    const int start = d_starts[g];
    const int end   = d_starts[g + 1];
    const int len   = end - start;
    const float cnt = fmaxf((float)len, 1.0f);

    __shared__ float red0[8], red1[8];
    const int wid = t >> 5, lid = t & 31;

    if (d_blzero) {
        float sp = 0.0f, sn = 0.0f;
        for (int i = start + t; i < end; i += HDIM) {
            float v = d_agg[i];
            sp += fmaxf(v, 0.0f);
            sn += fminf(v, 0.0f);
        }
        #pragma unroll
        for (int off = 16; off; off >>= 1) {
            sp += __shfl_xor_sync(0xffffffffu, sp, off);
            sn += __shfl_xor_sync(0xffffffffu, sn, off);
        }
        if (lid == 0) { red0[wid] = sp; red1[wid] = sn; }
        __syncthreads();
        if (t == 0) {
            float SP = 0.0f, SN = 0.0f;
            #pragma unroll
            for (int wI = 0; wI < 8; wI++) { SP += red0[wI]; SN += red1[wI]; }
            out[g] = fmaxf((d_P * SP + d_Nn * SN) / cnt + b_out[0], 0.0f);
        }
        return;
    }

    // exact slow path: one thread per feature
    const float w = W_l[t];
    const float b = b_l[t];
    float acc = 0.0f;
    __shared__ float sa[HDIM];
    for (int base = start; base < end; base += HDIM) {
        int n = min(HDIM, end - base);
        __syncthreads();
        if (t < n) sa[t] = d_agg[base + t];
        __syncthreads();
        float a0 = 0.f, a1 = 0.f, a2 = 0.f, a3 = 0.f;
        int j = 0;
        for (; j + 3 < n; j += 4) {
            a0 += fmaxf(fmaf(sa[j],     w, b), 0.0f);
            a1 += fmaxf(fmaf(sa[j + 1], w, b), 0.0f);
            a2 += fmaxf(fmaf(sa[j + 2], w, b), 0.0f);
            a3 += fmaxf(fmaf(sa[j + 3], w, b), 0.0f);
        }
        for (; j < n; j++)
            a0 += fmaxf(fmaf(sa[j], w, b), 0.0f);
        acc += (a0 + a1) + (a2 + a3);
    }
    float val = acc * W_out[t] / cnt;
    #pragma unroll
    for (int off = 16; off; off >>= 1)
        val += __shfl_xor_sync(0xffffffffu, val, off);
    if (lid == 0) red0[wid] = val;
    __syncthreads();
    if (t == 0) {
        float v = 0.0f;
        #pragma unroll
        for (int wI = 0; wI < 8; wI++) v += red0[wI];
        out[g] = fmaxf(v + b_out[0], 0.0f);
    }
}

// ---------------------------------------------------------------------------
// inputs (metadata order):
//   0: x float32[N]  1: ei int32[2E]  2: batch int32[N]
//   3: W_l f32[256]  4: b_l f32[256]  5: W_out f32[256]  6: b_out f32[1]
// out: float32 [128]
// ---------------------------------------------------------------------------
extern "C" void kernel_launch(void* const* d_in, const int* in_sizes, int n_in,
                              void* d_out, int out_size) {
    const float* x     = (const float*)d_in[0];
    const int*   ei    = (const int*)d_in[1];
    const int*   batch = (const int*)d_in[2];
    const float* W_l   = (const float*)d_in[3];
    const float* b_l   = (const float*)d_in[4];
    const float* W_out = (const float*)d_in[5];
    const float* b_out = (const float*)d_in[6];
    float*       out   = (float*)d_out;

    const int N = in_sizes[0];
    const int E = in_sizes[1] / 2;

    // zero agg via memset node
    void* aggp = nullptr;
    cudaGetSymbolAddress(&aggp, d_agg);
    cudaMemsetAsync(aggp, 0, (size_t)N * sizeof(float), 0);

    {
        const int threads    = 256;
        const int edgeWork   = (E + 7) / 8;
        const int edgeBlocks = (edgeWork + threads - 1) / threads;
        const int bndThreads = (N + 3) / 4;
        const int bndBlocks  = (bndThreads + threads - 1) / threads;
        edge_fused_kernel<<<edgeBlocks + bndBlocks + 1, threads>>>(
            ei, x, batch, W_l, b_l, W_out, E, N, edgeBlocks, bndBlocks);
    }
    {
        pool_kernel<<<NGRAPHS, HDIM>>>(W_l, b_l, W_out, b_out, out);
    }
}